// round 14
// baseline (speedup 1.0000x reference)
#include <cuda_runtime.h>

// Problem constants
#define PB 16384   // batch
#define PN 32      // keypoints
#define PK 16      // mixture components
#define KH 8       // components per thread (K split 2 ways)
#define MB 2       // samples per thread
#define TPB 128

// Packed per-(n,k) params, SoA over n within k, idx = k*32 + n:
//  g_pab[idx]        : (h0, h1, h2, q00)       h = -Q*mu
//  g_pab[idx + 512]  : (q01, q02, q11, q12)    (constant +8192B offset)
//  g_pc[idx]         : (q22, c)                c = mu^T Q mu + lc
// Q = Sigma^{-1} * (-0.5*log2e), lc = log2(w) - 0.5*log2((2pi)^3 det)
// Identity: earg = x.pd + h.x + c, where pd = Qx + h = Q(x-mu).
__device__ float4 g_pab[2 * PK * PN];
__device__ float2 g_pc[PK * PN];

__global__ void precompute_params(const float* __restrict__ means,
                                  const float* __restrict__ covs,
                                  const float* __restrict__ weights) {
    int t = blockIdx.x * 256 + threadIdx.x;
    if (t >= PN * PK) return;
    int n = t & 31;
    int k = t >> 5;
    int nk = n * PK + k;

    const float* c = covs + nk * 9;
    float c00 = c[0], c01 = c[1], c02 = c[2];
    float c11 = c[4], c12 = c[5], c22 = c[8];

    float m00 = c11 * c22 - c12 * c12;
    float m01 = c02 * c12 - c01 * c22;
    float m02 = c01 * c12 - c02 * c11;
    float det = c00 * m00 + c01 * m01 + c02 * m02;
    const float NH = -0.72134752044448170f;   // -(0.5*log2 e), folded into Q
    float inv = NH / det;

    float q00 = m00 * inv;
    float q01 = m01 * inv;
    float q02 = m02 * inv;
    float q11 = (c00 * c22 - c02 * c02) * inv;
    float q12 = (c01 * c02 - c00 * c12) * inv;
    float q22 = (c00 * c11 - c01 * c01) * inv;

    const float TWOPI3 = 248.05021344239853f; // (2*pi)^3
    float lc = log2f(weights[nk]) - 0.5f * log2f(TWOPI3 * det);

    const float* mu = means + nk * 3;
    float mx = mu[0], my = mu[1], mz = mu[2];
    // h = -Q*mu
    float h0 = -(q00 * mx + q01 * my + q02 * mz);
    float h1 = -(q01 * mx + q11 * my + q12 * mz);
    float h2 = -(q02 * mx + q12 * my + q22 * mz);
    // c = mu^T Q mu + lc = -(h . mu) + lc
    float cc = -(h0 * mx + h1 * my + h2 * mz) + lc;

    int idx = k * PN + n;
    g_pab[idx] = make_float4(h0, h1, h2, q00);
    g_pab[idx + PK * PN] = make_float4(q01, q02, q11, q12);
    g_pc[idx] = make_float2(q22, cc);
}

__device__ __forceinline__ float ex2a(float x) {
    float r; asm("ex2.approx.ftz.f32 %0,%1;" : "=f"(r) : "f"(x)); return r;
}
__device__ __forceinline__ float rcpa(float x) {
    float r; asm("rcp.approx.ftz.f32 %0,%1;" : "=f"(r) : "f"(x)); return r;
}

// 10 CTAs/SM -> 40 warps/SM (62.5%). MB=2 state is small enough that the
// 51-reg cap sits above natural usage (no spill expected).
__global__ void __launch_bounds__(TPB, 10) gmm_main(const float* __restrict__ kps,
                                                    float* __restrict__ out) {
    // index decode: lane = khalf*16 + n16 ; warp covers 16 consecutive n, both k-halves
    int gtid = blockIdx.x * TPB + threadIdx.x;
    int lane = gtid & 31;
    int kh   = lane >> 4;            // which half of K this thread computes
    int rest = gtid >> 5;
    int n    = ((rest & 1) << 4) | (lane & 15);
    int bg   = rest >> 1;            // 0 .. PB/MB-1
    int b0   = bg * MB;
    int obase = (b0 * PN + n) * 3;   // shared output/input element base

    float x[MB], y[MB], z[MB];
#pragma unroll
    for (int i = 0; i < MB; i++) {
        const float* p = kps + obase + i * (PN * 3);
        x[i] = p[0]; y[i] = p[1]; z[i] = p[2];
    }

    float pdf[MB], gx[MB], gy[MB], gz[MB];
#pragma unroll
    for (int i = 0; i < MB; i++) { pdf[i] = 0.0f; gx[i] = 0.0f; gy[i] = 0.0f; gz[i] = 0.0f; }

    int pidx = kh * (KH * PN) + n;

#pragma unroll
    for (int j = 0; j < KH; j++) {
        float4 pa = __ldg(g_pab + pidx + j * PN);            // h0,h1,h2,q00
        float4 pb = __ldg(g_pab + pidx + j * PN + PK * PN);  // q01,q02,q11,q12
        float2 pc = __ldg(g_pc  + pidx + j * PN);            // q22, c

#pragma unroll
        for (int i = 0; i < MB; i++) {
            // pd = Q x + h  (multipliers are loop-invariant x/y/z regs)
            float pd0 = fmaf(pa.w, x[i], fmaf(pb.x, y[i], fmaf(pb.y, z[i], pa.x)));
            float pd1 = fmaf(pb.x, x[i], fmaf(pb.z, y[i], fmaf(pb.w, z[i], pa.y)));
            float pd2 = fmaf(pb.y, x[i], fmaf(pb.w, y[i], fmaf(pc.x, z[i], pa.z)));
            // hx = h.x + c  (independent of pd chain)
            float hx  = fmaf(pa.x, x[i], fmaf(pa.y, y[i], fmaf(pa.z, z[i], pc.y)));
            // earg = x.pd + hx  ( = -0.5*log2e*maha + lc )
            float earg = fmaf(pd0, x[i], fmaf(pd1, y[i], fmaf(pd2, z[i], hx)));
            float e = ex2a(earg);
            pdf[i] += e;
            gx[i] = fmaf(e, pd0, gx[i]);
            gy[i] = fmaf(e, pd1, gy[i]);
            gz[i] = fmaf(e, pd2, gz[i]);
        }
    }

    // combine the two k-halves: partner lane is lane ^ 16 (same b,n)
#pragma unroll
    for (int i = 0; i < MB; i++) {
        pdf[i] += __shfl_xor_sync(0xFFFFFFFFu, pdf[i], 16);
        gx[i]  += __shfl_xor_sync(0xFFFFFFFFu, gx[i],  16);
        gy[i]  += __shfl_xor_sync(0xFFFFFFFFu, gy[i],  16);
        gz[i]  += __shfl_xor_sync(0xFFFFFFFFu, gz[i],  16);
    }

    // epilogue: gacc = (0.5*log2e)*grad_true (positive multiple);
    // (log2e/1100)/(0.5*log2e) = 1/550 -> mag = 2^(5*log2e - |gacc|/550)
    const float L2E_OVER_TAU = 0.19235933878519513f;  // log2e / 7.5
    const float MAG_C0 = 7.2134752044448170f;         // 5 * log2 e
    const float MAG_C1 = -1.0f / 550.0f;

    if (kh == 0) {
        // density sigmoid, lanes 0..15: contiguous 192B per (warp,i)
        float* od = out + obase;
#pragma unroll
        for (int i = 0; i < MB; i++) {
            float u = ex2a((40.0f - pdf[i]) * L2E_OVER_TAU);
            float s = rcpa(1.0f + u);
            od[0] = s; od[1] = s; od[2] = s;
            od += PN * 3;
        }
    } else {
        // gradient, lanes 16..31: contiguous 192B per (warp,i)
        float* og = out + (size_t)PB * PN * 3 + obase;
#pragma unroll
        for (int i = 0; i < MB; i++) {
            float s2 = fmaf(gx[i], gx[i], fmaf(gy[i], gy[i], gz[i] * gz[i]));
            float rinv = rsqrtf(s2);
            float gs = s2 * rinv;                    // |gacc|
            float mag = ex2a(fmaf(gs, MAG_C1, MAG_C0));
            float scale = rinv * mag;                // ETA=1; sign correct
            og[0] = gx[i] * scale;
            og[1] = gy[i] * scale;
            og[2] = gz[i] * scale;
            og += PN * 3;
        }
    }
}

extern "C" void kernel_launch(void* const* d_in, const int* in_sizes, int n_in,
                              void* d_out, int out_size) {
    const float* kps     = (const float*)d_in[0];
    const float* means   = (const float*)d_in[1];
    const float* covs    = (const float*)d_in[2];
    const float* weights = (const float*)d_in[3];
    float* out = (float*)d_out;

    precompute_params<<<2, 256>>>(means, covs, weights);

    int total_threads = (PB / MB) * PN * 2;     // 524288 (k split 2-way)
    gmm_main<<<total_threads / TPB, TPB>>>(kps, out);
}

// round 16
// speedup vs baseline: 1.0214x; 1.0214x over previous
#include <cuda_runtime.h>

// Problem constants
#define PB 16384   // batch
#define PN 32      // keypoints
#define PK 16      // mixture components
#define KH 8       // components per thread (K split 2 ways)
#define MB 4       // samples per thread
#define TPB 128

// Packed per-(n,k) params, SoA over n within k, idx = k*32 + n:
//  g_pab[idx]        : (h0, h1, h2, q00)       h = -Q*mu
//  g_pab[idx + 512]  : (q01, q02, q11, q12)    (constant +8192B offset)
//  g_pc[idx]         : (q22, c)                c = mu^T Q mu + lc
// Q = Sigma^{-1} * (-0.5*log2e), lc = log2(w) - 0.5*log2((2pi)^3 det)
// Identity: earg = x.pd + h.x + c, where pd = Qx + h = Q(x-mu).
__device__ float4 g_pab[2 * PK * PN];
__device__ float2 g_pc[PK * PN];

// Coalesced mapping: thread t handles nk = t (consecutive threads read
// consecutive 36B cov rows -> 9 lines/warp instead of 32 scattered).
__global__ void precompute_params(const float* __restrict__ means,
                                  const float* __restrict__ covs,
                                  const float* __restrict__ weights) {
    int t = threadIdx.x;
    if (t >= PN * PK) return;
    int n = t >> 4;          // nk = n*PK + k = t
    int k = t & 15;
    int nk = t;

    const float* c = covs + nk * 9;
    float c00 = c[0], c01 = c[1], c02 = c[2];
    float c11 = c[4], c12 = c[5], c22 = c[8];

    float m00 = c11 * c22 - c12 * c12;
    float m01 = c02 * c12 - c01 * c22;
    float m02 = c01 * c12 - c02 * c11;
    float det = c00 * m00 + c01 * m01 + c02 * m02;
    const float NH = -0.72134752044448170f;   // -(0.5*log2 e), folded into Q
    float inv = NH / det;

    float q00 = m00 * inv;
    float q01 = m01 * inv;
    float q02 = m02 * inv;
    float q11 = (c00 * c22 - c02 * c02) * inv;
    float q12 = (c01 * c02 - c00 * c12) * inv;
    float q22 = (c00 * c11 - c01 * c01) * inv;

    const float TWOPI3 = 248.05021344239853f; // (2*pi)^3
    float lc = log2f(weights[nk]) - 0.5f * log2f(TWOPI3 * det);

    const float* mu = means + nk * 3;
    float mx = mu[0], my = mu[1], mz = mu[2];
    // h = -Q*mu
    float h0 = -(q00 * mx + q01 * my + q02 * mz);
    float h1 = -(q01 * mx + q11 * my + q12 * mz);
    float h2 = -(q02 * mx + q12 * my + q22 * mz);
    // c = mu^T Q mu + lc = -(h . mu) + lc
    float cc = -(h0 * mx + h1 * my + h2 * mz) + lc;

    int idx = k * PN + n;
    g_pab[idx] = make_float4(h0, h1, h2, q00);
    g_pab[idx + PK * PN] = make_float4(q01, q02, q11, q12);
    g_pc[idx] = make_float2(q22, cc);
}

__device__ __forceinline__ float ex2a(float x) {
    float r; asm("ex2.approx.ftz.f32 %0,%1;" : "=f"(r) : "f"(x)); return r;
}
__device__ __forceinline__ float rcpa(float x) {
    float r; asm("rcp.approx.ftz.f32 %0,%1;" : "=f"(r) : "f"(x)); return r;
}

__global__ void __launch_bounds__(TPB, 8) gmm_main(const float* __restrict__ kps,
                                                   float* __restrict__ out) {
    // index decode: lane = khalf*16 + n16 ; warp covers 16 consecutive n, both k-halves
    int gtid = blockIdx.x * TPB + threadIdx.x;
    int lane = gtid & 31;
    int kh   = lane >> 4;            // which half of K this thread computes
    int rest = gtid >> 5;
    int n    = ((rest & 1) << 4) | (lane & 15);
    int bg   = rest >> 1;            // 0 .. PB/MB-1
    int b0   = bg * MB;
    int obase = (b0 * PN + n) * 3;   // shared output/input element base

    float x[MB], y[MB], z[MB];
#pragma unroll
    for (int i = 0; i < MB; i++) {
        const float* p = kps + obase + i * (PN * 3);
        x[i] = p[0]; y[i] = p[1]; z[i] = p[2];
    }

    float pdf[MB], gx[MB], gy[MB], gz[MB];
#pragma unroll
    for (int i = 0; i < MB; i++) { pdf[i] = 0.0f; gx[i] = 0.0f; gy[i] = 0.0f; gz[i] = 0.0f; }

    int pidx = kh * (KH * PN) + n;

#pragma unroll
    for (int j = 0; j < KH; j++) {
        float4 pa = __ldg(g_pab + pidx + j * PN);            // h0,h1,h2,q00
        float4 pb = __ldg(g_pab + pidx + j * PN + PK * PN);  // q01,q02,q11,q12
        float2 pc = __ldg(g_pc  + pidx + j * PN);            // q22, c

#pragma unroll
        for (int i = 0; i < MB; i++) {
            // pd = Q x + h  (multipliers are loop-invariant x/y/z regs)
            float pd0 = fmaf(pa.w, x[i], fmaf(pb.x, y[i], fmaf(pb.y, z[i], pa.x)));
            float pd1 = fmaf(pb.x, x[i], fmaf(pb.z, y[i], fmaf(pb.w, z[i], pa.y)));
            float pd2 = fmaf(pb.y, x[i], fmaf(pb.w, y[i], fmaf(pc.x, z[i], pa.z)));
            // hx = h.x + c  (independent of pd chain)
            float hx  = fmaf(pa.x, x[i], fmaf(pa.y, y[i], fmaf(pa.z, z[i], pc.y)));
            // earg = x.pd + hx  ( = -0.5*log2e*maha + lc )
            float earg = fmaf(pd0, x[i], fmaf(pd1, y[i], fmaf(pd2, z[i], hx)));
            float e = ex2a(earg);
            pdf[i] += e;
            gx[i] = fmaf(e, pd0, gx[i]);
            gy[i] = fmaf(e, pd1, gy[i]);
            gz[i] = fmaf(e, pd2, gz[i]);
        }
    }

    // combine the two k-halves: partner lane is lane ^ 16 (same b,n)
#pragma unroll
    for (int i = 0; i < MB; i++) {
        pdf[i] += __shfl_xor_sync(0xFFFFFFFFu, pdf[i], 16);
        gx[i]  += __shfl_xor_sync(0xFFFFFFFFu, gx[i],  16);
        gy[i]  += __shfl_xor_sync(0xFFFFFFFFu, gy[i],  16);
        gz[i]  += __shfl_xor_sync(0xFFFFFFFFu, gz[i],  16);
    }

    // epilogue: gacc = (0.5*log2e)*grad_true (positive multiple);
    // (log2e/1100)/(0.5*log2e) = 1/550 -> mag = 2^(5*log2e - |gacc|/550)
    const float L2E_OVER_TAU = 0.19235933878519513f;  // log2e / 7.5
    const float MAG_C0 = 7.2134752044448170f;         // 5 * log2 e
    const float MAG_C1 = -1.0f / 550.0f;

    if (kh == 0) {
        // density sigmoid, lanes 0..15: contiguous 192B per (warp,i)
        float* od = out + obase;
#pragma unroll
        for (int i = 0; i < MB; i++) {
            float u = ex2a((40.0f - pdf[i]) * L2E_OVER_TAU);
            float s = rcpa(1.0f + u);
            od[0] = s; od[1] = s; od[2] = s;
            od += PN * 3;
        }
    } else {
        // gradient, lanes 16..31: contiguous 192B per (warp,i)
        float* og = out + (size_t)PB * PN * 3 + obase;
#pragma unroll
        for (int i = 0; i < MB; i++) {
            float s2 = fmaf(gx[i], gx[i], fmaf(gy[i], gy[i], gz[i] * gz[i]));
            float rinv = rsqrtf(s2);
            float gs = s2 * rinv;                    // |gacc|
            float mag = ex2a(fmaf(gs, MAG_C1, MAG_C0));
            float scale = rinv * mag;                // ETA=1; sign correct
            og[0] = gx[i] * scale;
            og[1] = gy[i] * scale;
            og[2] = gz[i] * scale;
            og += PN * 3;
        }
    }
}

extern "C" void kernel_launch(void* const* d_in, const int* in_sizes, int n_in,
                              void* d_out, int out_size) {
    const float* kps     = (const float*)d_in[0];
    const float* means   = (const float*)d_in[1];
    const float* covs    = (const float*)d_in[2];
    const float* weights = (const float*)d_in[3];
    float* out = (float*)d_out;

    precompute_params<<<1, 512>>>(means, covs, weights);

    int total_threads = (PB / MB) * PN * 2;     // 262144 (k split 2-way)
    gmm_main<<<total_threads / TPB, TPB>>>(kps, out);
}